// round 9
// baseline (speedup 1.0000x reference)
#include <cuda_runtime.h>
#include <math.h>

// Fixed problem shapes
#define BB 4
#define NN 2048
#define FF 256
#define HH 512
#define EE 65536
#define ROWS (BB*NN)          // 8192
#define TOT  (ROWS*FF)        // 2097152

// ---------------- scratch (device globals; no cudaMalloc allowed) ----------
__device__ float g_kbuf[7 * TOT];
__device__ float g_ya[TOT];
__device__ float g_yb[TOT];
__device__ float g_yi[TOT];
__device__ float g_h1[ROWS * HH];
__device__ float g_h2[ROWS * HH];
__device__ float g_tmp[TOT];
__device__ float g_g1[TOT];
__device__ float g_dc[ROWS];
__device__ float g_ctx[BB * HH];
__device__ float g_ew[EE];
__device__ float g_val[EE];
__device__ float g_dis[NN];
__device__ float g_diag[NN];
__device__ int   g_deg[NN];
__device__ int   g_rowcnt[NN];
__device__ int   g_fill[NN];
__device__ int   g_rowptr[NN + 1];
__device__ int   g_colidx[EE];

// ---------------- graph / Laplacian build ----------------------------------

__global__ void init_graph_kernel(int* deg, int* rowcnt, int* fill) {
    int i = blockIdx.x * 256 + threadIdx.x;
    if (i < NN) { deg[i] = 1; rowcnt[i] = 0; fill[i] = 0; }  // deg=1: self loop
}

__global__ void edgew_kernel(const float* __restrict__ attr,
                             const float* __restrict__ w1, const float* __restrict__ b1,
                             const float* __restrict__ w2, const float* __restrict__ b2,
                             float* __restrict__ ew) {
    int e = blockIdx.x * 256 + threadIdx.x;
    if (e >= EE) return;
    float a = attr[e];
    float s = b2[0];
    #pragma unroll
    for (int j = 0; j < 32; j++) {
        float h = fmaxf(fmaf(a, w1[j], b1[j]), 0.f);
        s = fmaf(h, w2[j], s);
    }
    ew[e] = 1.f / (1.f + expf(-s));
}

__global__ void count_kernel(const int* __restrict__ ei, int* rowcnt, int* deg) {
    int e = blockIdx.x * 256 + threadIdx.x;
    if (e >= EE) return;
    atomicAdd(&rowcnt[ei[e]], 1);       // row
    atomicAdd(&deg[ei[EE + e]], 1);     // col (unweighted degree)
}

__global__ void disdiag_kernel(const int* __restrict__ deg, float* dis, float* diag) {
    int i = blockIdx.x * 256 + threadIdx.x;
    if (i >= NN) return;
    float d = rsqrtf((float)deg[i]);
    dis[i] = d;
    diag[i] = 1.f - d * d;   // L = I - adj; self-loop weight is dis[i]^2
}

// exclusive scan of 2048 counts -> rowptr (single block, 256 threads x 8)
__global__ void scan_kernel(const int* __restrict__ cnt, int* __restrict__ rowptr) {
    __shared__ int part[256];
    int t = threadIdx.x;
    int loc[8]; int s = 0;
    #pragma unroll
    for (int i = 0; i < 8; i++) { loc[i] = s; s += cnt[t * 8 + i]; }
    part[t] = s;
    __syncthreads();
    for (int off = 1; off < 256; off <<= 1) {
        int v = (t >= off) ? part[t - off] : 0;
        __syncthreads();
        part[t] += v;
        __syncthreads();
    }
    int base = t ? part[t - 1] : 0;
    #pragma unroll
    for (int i = 0; i < 8; i++) rowptr[t * 8 + i] = base + loc[i];
    if (t == 255) rowptr[NN] = part[255];
}

__global__ void scatter_kernel(const int* __restrict__ ei, const float* __restrict__ ew,
                               const float* __restrict__ dis, const int* __restrict__ rowptr,
                               int* fill, int* __restrict__ colidx, float* __restrict__ val) {
    int e = blockIdx.x * 256 + threadIdx.x;
    if (e >= EE) return;
    int r = ei[e], c = ei[EE + e];
    int pos = rowptr[r] + atomicAdd(&fill[r], 1);
    colidx[pos] = c;
    val[pos] = dis[r] * ew[e] * dis[c];
}

// ---------------- context projection (once per launch) ---------------------
// ctx_proj[b,n] = sum_k context[b,k] * td_w1[FF+k, n] + td_b1[n]
__global__ void ctxproj_kernel(const float* __restrict__ context,
                               const float* __restrict__ w1, const float* __restrict__ b1,
                               float* __restrict__ out) {
    int b = blockIdx.x, n = threadIdx.x;  // 512 threads
    float s = b1[n];
    for (int k = 0; k < FF; k++)
        s = fmaf(context[b * FF + k], w1[(size_t)(FF + k) * HH + n], s);
    out[b * HH + n] = s;
}

// ---------------- SGEMM: C[M,N] = A[M,K] @ B[K,N] (+ biases, opt relu) -----
// BM=128, BN=64, BK=32, 256 threads, 8x4 per thread.
__global__ __launch_bounds__(256) void sgemm_kernel(
    const float* __restrict__ A, const float* __restrict__ B,
    float* __restrict__ C, int M, int N, int K, int ldb,
    const float* __restrict__ colBias,      // [N] or null
    const float* __restrict__ batchBias,    // [(row>>11)*N + col] or null
    int doRelu)
{
    __shared__ float As[32][129];   // padded: conflict-free transposed stores
    __shared__ float Bs[32][64];
    int tid = threadIdx.x;
    int bn = blockIdx.x, bm = blockIdx.y;
    int tr = tid >> 4, tc = tid & 15;
    int aRow = tid >> 3, aCol = (tid & 7) << 2;
    int bRow = tid >> 4, bCol = (tid & 15) << 2;

    const float* Ab = A + (size_t)bm * 128 * K;
    const float* Bb = B + (size_t)bn * 64;

    float acc[8][4];
    #pragma unroll
    for (int i = 0; i < 8; i++)
        #pragma unroll
        for (int j = 0; j < 4; j++) acc[i][j] = 0.f;

    for (int k0 = 0; k0 < K; k0 += 32) {
        #pragma unroll
        for (int it = 0; it < 4; ++it) {
            int r = aRow + 32 * it;
            float4 v = *(const float4*)(Ab + (size_t)r * K + k0 + aCol);
            As[aCol + 0][r] = v.x; As[aCol + 1][r] = v.y;
            As[aCol + 2][r] = v.z; As[aCol + 3][r] = v.w;
        }
        #pragma unroll
        for (int it = 0; it < 2; ++it) {
            int r = bRow + 16 * it;
            *(float4*)&Bs[r][bCol] = *(const float4*)(Bb + (size_t)(k0 + r) * ldb + bCol);
        }
        __syncthreads();
        #pragma unroll
        for (int k = 0; k < 32; k++) {
            float ra[8], rb[4];
            #pragma unroll
            for (int i = 0; i < 8; i++) ra[i] = As[k][tr * 8 + i];
            #pragma unroll
            for (int j = 0; j < 4; j++) rb[j] = Bs[k][tc * 4 + j];
            #pragma unroll
            for (int i = 0; i < 8; i++)
                #pragma unroll
                for (int j = 0; j < 4; j++)
                    acc[i][j] = fmaf(ra[i], rb[j], acc[i][j]);
        }
        __syncthreads();
    }

    int col = bn * 64 + tc * 4;
    float4 cb = make_float4(0.f, 0.f, 0.f, 0.f);
    if (colBias) cb = *(const float4*)(colBias + col);
    #pragma unroll
    for (int i = 0; i < 8; i++) {
        int row = bm * 128 + tr * 8 + i;
        float bx = cb.x, by = cb.y, bz = cb.z, bw = cb.w;
        if (batchBias) {
            float4 b2 = *(const float4*)(batchBias + (size_t)(row >> 11) * N + col);
            bx += b2.x; by += b2.y; bz += b2.z; bw += b2.w;
        }
        float4 o;
        o.x = acc[i][0] + bx; o.y = acc[i][1] + by;
        o.z = acc[i][2] + bz; o.w = acc[i][3] + bw;
        if (doRelu) {
            o.x = fmaxf(o.x, 0.f); o.y = fmaxf(o.y, 0.f);
            o.z = fmaxf(o.z, 0.f); o.w = fmaxf(o.w, 0.f);
        }
        *(float4*)(C + (size_t)row * N + col) = o;
    }
}

// ---------------- LayerNorm(width=512) + ReLU, in-place, two-pass ----------
__global__ __launch_bounds__(256) void ln_relu_kernel(float* __restrict__ x,
                                                      const float* __restrict__ g,
                                                      const float* __restrict__ b) {
    int row = blockIdx.x;
    float* xr = x + (size_t)row * HH;
    int t = threadIdx.x;
    float2 v = ((float2*)xr)[t];
    __shared__ float ws[8];
    __shared__ float mu_s, inv_s;
    int lane = t & 31, w = t >> 5;

    float s = v.x + v.y;
    #pragma unroll
    for (int o = 16; o; o >>= 1) s += __shfl_xor_sync(0xffffffffu, s, o);
    if (!lane) ws[w] = s;
    __syncthreads();
    if (t == 0) {
        float tot = 0.f;
        #pragma unroll
        for (int i = 0; i < 8; i++) tot += ws[i];
        mu_s = tot * (1.f / HH);
    }
    __syncthreads();
    float mu = mu_s;
    float dx = v.x - mu, dy = v.y - mu;
    s = dx * dx + dy * dy;
    #pragma unroll
    for (int o = 16; o; o >>= 1) s += __shfl_xor_sync(0xffffffffu, s, o);
    if (!lane) ws[w] = s;
    __syncthreads();
    if (t == 0) {
        float tot = 0.f;
        #pragma unroll
        for (int i = 0; i < 8; i++) tot += ws[i];
        inv_s = rsqrtf(tot * (1.f / HH) + 1e-5f);
    }
    __syncthreads();
    float inv = inv_s;
    float2 gv = ((const float2*)g)[t];
    float2 bv = ((const float2*)b)[t];
    float2 o;
    o.x = fmaxf(fmaf(dx * inv, gv.x, bv.x), 0.f);
    o.y = fmaxf(fmaf(dy * inv, gv.y, bv.y), 0.f);
    ((float2*)xr)[t] = o;
}

// ---------------- dcoef: sigmoid(row-dot) ----------------------------------
__global__ __launch_bounds__(256) void dcoef_kernel(const float* __restrict__ g1,
                                                    const float* __restrict__ w2,
                                                    const float* __restrict__ b2,
                                                    float* __restrict__ dc) {
    int lane = threadIdx.x & 31, w = threadIdx.x >> 5;
    int row = blockIdx.x * 8 + w;
    const float* r = g1 + (size_t)row * FF;
    float s = 0.f;
    #pragma unroll
    for (int j = 0; j < FF / 32; j++)
        s = fmaf(r[lane + j * 32], w2[lane + j * 32], s);
    #pragma unroll
    for (int o = 16; o; o >>= 1) s += __shfl_xor_sync(0xffffffffu, s, o);
    if (!lane) dc[row] = 1.f / (1.f + expf(-(s + b2[0])));
}

// ---------------- fused SpMM diffusion + combine ----------------------------
// kout = temporal - dc * (diag[i]*y[b,i,:] - sum_e val[e]*y[b,col[e],:])
__global__ __launch_bounds__(256) void spmm_kernel(
    const float* __restrict__ y, const float* __restrict__ temporal,
    const float* __restrict__ dc, const int* __restrict__ rowptr,
    const int* __restrict__ colidx, const float* __restrict__ val,
    const float* __restrict__ diag, float* __restrict__ kout)
{
    int i = blockIdx.x, b = blockIdx.y, f = threadIdx.x;
    const float* yb = y + (size_t)b * NN * FF;
    float acc = diag[i] * yb[(size_t)i * FF + f];
    int e1 = rowptr[i + 1];
    for (int e = rowptr[i]; e < e1; ++e)
        acc = fmaf(-val[e], yb[(size_t)colidx[e] * FF + f], acc);
    size_t o = ((size_t)b * NN + i) * FF + f;
    kout[o] = temporal[o] - dc[b * NN + i] * acc;
}

// ---------------- stage combine: out = y + sum c_j * k_j -------------------
__global__ __launch_bounds__(256) void axpy_kernel(
    float4* __restrict__ out, const float4* __restrict__ y,
    const float4* k0, const float4* k1, const float4* k2,
    const float4* k3, const float4* k4, const float4* k5,
    float c0, float c1, float c2, float c3, float c4, float c5)
{
    int i = blockIdx.x * 256 + threadIdx.x;  // grid = TOT/4/256
    float4 v = y[i];
#define ACCK(kk, cc) if (kk) { float4 a = kk[i]; \
    v.x = fmaf(cc, a.x, v.x); v.y = fmaf(cc, a.y, v.y); \
    v.z = fmaf(cc, a.z, v.z); v.w = fmaf(cc, a.w, v.w); }
    ACCK(k0, c0) ACCK(k1, c1) ACCK(k2, c2) ACCK(k3, c3) ACCK(k4, c4) ACCK(k5, c5)
#undef ACCK
    out[i] = v;
}

__global__ void copy_kernel(float4* __restrict__ dst, const float4* __restrict__ src) {
    int i = blockIdx.x * 256 + threadIdx.x;
    dst[i] = src[i];
}

// ---------------- host orchestration ----------------------------------------

struct Wts {
    const float *td_w1, *td_b2, *ln1_g, *ln1_b, *td_w2, *ln2_g, *ln2_b,
                *td_w3, *td_b3, *df_w1, *df_b1, *df_w2, *df_b2;
    float *h1, *h2, *tmp, *g1, *dc, *ctx;
    const int *rowptr, *colidx;
    const float *val, *diag;
};

static void feval(const float* y, float* kout, const Wts& w) {
    dim3 gBig(HH / 64, ROWS / 128);     // (8, 64)
    dim3 gSmall(FF / 64, ROWS / 128);   // (4, 64)
    sgemm_kernel<<<gBig, 256>>>(y, w.td_w1, w.h1, ROWS, HH, FF, HH, nullptr, w.ctx, 0);
    ln_relu_kernel<<<ROWS, 256>>>(w.h1, w.ln1_g, w.ln1_b);
    sgemm_kernel<<<gBig, 256>>>(w.h1, w.td_w2, w.h2, ROWS, HH, HH, HH, w.td_b2, nullptr, 0);
    ln_relu_kernel<<<ROWS, 256>>>(w.h2, w.ln2_g, w.ln2_b);
    sgemm_kernel<<<gSmall, 256>>>(w.h2, w.td_w3, w.tmp, ROWS, FF, HH, FF, w.td_b3, nullptr, 0);
    sgemm_kernel<<<gSmall, 256>>>(y, w.df_w1, w.g1, ROWS, FF, FF, FF, w.df_b1, nullptr, 1);
    dcoef_kernel<<<ROWS / 8, 256>>>(w.g1, w.df_w2, w.df_b2, w.dc);
    spmm_kernel<<<dim3(NN, BB), 256>>>(y, w.tmp, w.dc, w.rowptr, w.colidx, w.val, w.diag, kout);
}

extern "C" void kernel_launch(void* const* d_in, const int* in_sizes, int n_in,
                              void* d_out, int out_size)
{
    const float* state     = (const float*)d_in[0];
    const float* context   = (const float*)d_in[1];
    const float* edge_attr = (const float*)d_in[2];
    const int*   edge_idx  = (const int*)  d_in[3];
    const float* ew_w1 = (const float*)d_in[4];
    const float* ew_b1 = (const float*)d_in[5];
    const float* ew_w2 = (const float*)d_in[6];
    const float* ew_b2 = (const float*)d_in[7];
    const float* td_w1 = (const float*)d_in[8];
    const float* td_b1 = (const float*)d_in[9];
    const float* ln1_g = (const float*)d_in[10];
    const float* ln1_b = (const float*)d_in[11];
    const float* td_w2 = (const float*)d_in[12];
    const float* td_b2 = (const float*)d_in[13];
    const float* ln2_g = (const float*)d_in[14];
    const float* ln2_b = (const float*)d_in[15];
    const float* td_w3 = (const float*)d_in[16];
    const float* td_b3 = (const float*)d_in[17];
    const float* df_w1 = (const float*)d_in[18];
    const float* df_b1 = (const float*)d_in[19];
    const float* df_w2 = (const float*)d_in[20];
    const float* df_b2 = (const float*)d_in[21];

    // resolve scratch symbols
    float *kbuf, *ya, *yb, *yi, *h1, *h2, *tmp, *g1, *dc, *ctx;
    float *ew, *val, *dis, *diag;
    int *deg, *rowcnt, *fill, *rowptr, *colidx;
    cudaGetSymbolAddress((void**)&kbuf,  g_kbuf);
    cudaGetSymbolAddress((void**)&ya,    g_ya);
    cudaGetSymbolAddress((void**)&yb,    g_yb);
    cudaGetSymbolAddress((void**)&yi,    g_yi);
    cudaGetSymbolAddress((void**)&h1,    g_h1);
    cudaGetSymbolAddress((void**)&h2,    g_h2);
    cudaGetSymbolAddress((void**)&tmp,   g_tmp);
    cudaGetSymbolAddress((void**)&g1,    g_g1);
    cudaGetSymbolAddress((void**)&dc,    g_dc);
    cudaGetSymbolAddress((void**)&ctx,   g_ctx);
    cudaGetSymbolAddress((void**)&ew,    g_ew);
    cudaGetSymbolAddress((void**)&val,   g_val);
    cudaGetSymbolAddress((void**)&dis,   g_dis);
    cudaGetSymbolAddress((void**)&diag,  g_diag);
    cudaGetSymbolAddress((void**)&deg,   g_deg);
    cudaGetSymbolAddress((void**)&rowcnt,g_rowcnt);
    cudaGetSymbolAddress((void**)&fill,  g_fill);
    cudaGetSymbolAddress((void**)&rowptr,g_rowptr);
    cudaGetSymbolAddress((void**)&colidx,g_colidx);

    // ---- 1. Build normalized Laplacian as CSR (once per launch) ----
    init_graph_kernel<<<NN / 256, 256>>>(deg, rowcnt, fill);
    edgew_kernel<<<EE / 256, 256>>>(edge_attr, ew_w1, ew_b1, ew_w2, ew_b2, ew);
    count_kernel<<<EE / 256, 256>>>(edge_idx, rowcnt, deg);
    disdiag_kernel<<<NN / 256, 256>>>(deg, dis, diag);
    scan_kernel<<<1, 256>>>(rowcnt, rowptr);
    scatter_kernel<<<EE / 256, 256>>>(edge_idx, ew, dis, rowptr, fill, colidx, val);

    // ---- 2. Constant context projection (absorbs td_b1) ----
    ctxproj_kernel<<<BB, HH>>>(context, td_w1, td_b1, ctx);

    // ---- 3. y0 = state ----
    copy_kernel<<<TOT / 4 / 256, 256>>>((float4*)ya, (const float4*)state);

    Wts w;
    w.td_w1 = td_w1; w.td_b2 = td_b2; w.ln1_g = ln1_g; w.ln1_b = ln1_b;
    w.td_w2 = td_w2; w.ln2_g = ln2_g; w.ln2_b = ln2_b;
    w.td_w3 = td_w3; w.td_b3 = td_b3;
    w.df_w1 = df_w1; w.df_b1 = df_b1; w.df_w2 = df_w2; w.df_b2 = df_b2;
    w.h1 = h1; w.h2 = h2; w.tmp = tmp; w.g1 = g1; w.dc = dc; w.ctx = ctx;
    w.rowptr = rowptr; w.colidx = colidx; w.val = val; w.diag = diag;

    // ---- 4. dopri5, 4 fixed steps, FSAL reuse ----
    const double dt = 0.25;
    const double A2[1] = {1.0 / 5};
    const double A3[2] = {3.0 / 40, 9.0 / 40};
    const double A4[3] = {44.0 / 45, -56.0 / 15, 32.0 / 9};
    const double A5[4] = {19372.0 / 6561, -25360.0 / 2187, 64448.0 / 6561, -212.0 / 729};
    const double A6[5] = {9017.0 / 3168, -355.0 / 33, 46732.0 / 5247, 49.0 / 176, -5103.0 / 18656};
    const double BW[6] = {35.0 / 384, 0.0, 500.0 / 1113, 125.0 / 192, -2187.0 / 6784, 11.0 / 84};
    const double* Arows[5] = {A2, A3, A4, A5, A6};

    float* kp[7];
    for (int i = 0; i < 7; i++) kp[i] = kbuf + (size_t)i * TOT;

    float* ycur = ya;
    float* yoth = yb;
    const int nAx = TOT / 4 / 256;

    for (int s = 0; s < 4; ++s) {
        if (s == 0) feval(ycur, kp[0], w);   // else FSAL: kp[0] = prev step's k7

        for (int i = 1; i <= 5; ++i) {
            const double* a = Arows[i - 1];
            const float4* ks[6] = {nullptr, nullptr, nullptr, nullptr, nullptr, nullptr};
            float cs[6] = {0, 0, 0, 0, 0, 0};
            for (int j = 0; j < i; j++) { ks[j] = (const float4*)kp[j]; cs[j] = (float)(dt * a[j]); }
            axpy_kernel<<<nAx, 256>>>((float4*)yi, (const float4*)ycur,
                                      ks[0], ks[1], ks[2], ks[3], ks[4], ks[5],
                                      cs[0], cs[1], cs[2], cs[3], cs[4], cs[5]);
            feval(yi, kp[i], w);
        }

        float* ynext = (s == 3) ? (float*)d_out : yoth;
        axpy_kernel<<<nAx, 256>>>((float4*)ynext, (const float4*)ycur,
                                  (const float4*)kp[0], nullptr,
                                  (const float4*)kp[2], (const float4*)kp[3],
                                  (const float4*)kp[4], (const float4*)kp[5],
                                  (float)(dt * BW[0]), 0.f,
                                  (float)(dt * BW[2]), (float)(dt * BW[3]),
                                  (float)(dt * BW[4]), (float)(dt * BW[5]));

        if (s < 3) {
            // FSAL: k7 = f(ynew) becomes next step's k1
            feval(ynext, kp[6], w);
            float* t = kp[0]; kp[0] = kp[6]; kp[6] = t;
            yoth = ycur;
            ycur = ynext;
        }
    }
}